// round 14
// baseline (speedup 1.0000x reference)
#include <cuda_runtime.h>
#include <math.h>

#define NBINS   15
#define NTR     20000
#define NTE     10000
#define NBATCH  1024
#define NMC     10000
#define NCLS    10
#define NPTS_TOT (NTR + NTE + NBATCH)

#define GRIDW   16
#define CELLSZ  0.75f
#define INVCELL (1.0f / 0.75f)
#define DOMLO   (-6.0f)
#define RC      1.4f

#define CEXP       8.014972449383130f
#define KDE_NORM_F 0.56548667764616278f

#define NQWMAX  704
#define NSLOT   64           // CHPTS*NSLOT >= NPTS_TOT
#define CHPTS   512
#define NBLKA   296
#define MAXROWS 16

#define NPREP   30
#define STHREADS 1024
#define SWARPS   32

__device__ int    g_htr_part[NPREP][NBINS];
__device__ int    g_hte_part[NPREP][NBINS];
__device__ int    g_c_part[NPREP];
__device__ int    g_htr[NBINS], g_hte[NBINS], g_c;
__device__ int    g_qn[NBINS];
__device__ int    g_cs_p[3][257];
__device__ int    g_wq_bin[NQWMAX];
__device__ int    g_wq_first[NBINS];
__device__ int    g_ntask, g_task_ctr, g_done;
__device__ int    g_qw_span[NQWMAX];
__device__ int    g_qw_nrows[NQWMAX];
__device__ int4   g_qw_rowA[NQWMAX * MAXROWS];   // {cum, jtr0, jte0, jb0}
__device__ int4   g_qw_rowB[NQWMAX * MAXROWS];   // {Ltr, Lte, Lb, 0}
__device__ float4 g_spts[NPTS_TOT];
__device__ float4 g_qs[NBINS * NMC];
__device__ float4 g_A[NQWMAX * 32][NSLOT];       // query-major: warp-per-query fold
__device__ double g_partial[NQWMAX];

__device__ __forceinline__ float ex2f(float x) {
    float r;
    asm("ex2.approx.ftz.f32 %0, %1;" : "=f"(r) : "f"(x));
    return r;
}
__device__ __forceinline__ float bin_lo(int b) { return (float)b * (1.0f / 15.0f); }
__device__ __forceinline__ float bin_hi(int b) { return (b == NBINS - 1) ? 1.0f : (float)(b + 1) * (1.0f / 15.0f); }

__device__ __forceinline__ int cell_of(float x, float y) {
    int cx = min(max((int)floorf((x - DOMLO) * INVCELL), 0), GRIDW - 1);
    int cy = min(max((int)floorf((y - DOMLO) * INVCELL), 0), GRIDW - 1);
    return cy * GRIDW + cx;
}
__device__ __forceinline__ int cell_of_snake(float x, float y) {
    int cx = min(max((int)floorf((x - DOMLO) * INVCELL), 0), GRIDW - 1);
    int cy = min(max((int)floorf((y - DOMLO) * INVCELL), 0), GRIDW - 1);
    if (cy & 1) cx = GRIDW - 1 - cx;
    return cy * GRIDW + cx;
}

// ---------------------------------------------------------------------------
// Fused sort + prep. Blocks 0..17: counting sorts. Blocks 18..47: prep.
// ---------------------------------------------------------------------------
__global__ __launch_bounds__(STHREADS) void ec_sort(
    const float2* __restrict__ train, const float2* __restrict__ test,
    const float2* __restrict__ batch, const int* __restrict__ y,
    const int* __restrict__ pred, const float2* __restrict__ mc,
    const float* __restrict__ W, const float* __restrict__ bvec,
    const float* __restrict__ tp, const float* __restrict__ sp)
{
    int blkid = blockIdx.x;
    int t = threadIdx.x, w = t >> 5, lane = t & 31;

    if (blkid >= 18) {
        __shared__ int h1[NBINS], h2[NBINS], sc;
        int blk = blkid - 18;
        if (t < NBINS) { h1[t] = 0; h2[t] = 0; }
        if (t == 0) sc = 0;
        __syncthreads();

        int gs = NPREP * STHREADS;
        int g  = blk * STHREADS + t;

        int c = 0;
        for (int i = g; i < NBATCH; i += gs) c += (y[i] == pred[i]) ? 1 : 0;
        #pragma unroll
        for (int o = 16; o; o >>= 1) c += __shfl_xor_sync(0xffffffffu, c, o);
        if ((t & 31) == 0 && c) atomicAdd(&sc, c);

        for (int i = g; i < NTR; i += gs) {
            float p = tp[i];
            #pragma unroll
            for (int b = 0; b < NBINS; b++)
                if (p > bin_lo(b) && p <= bin_hi(b)) atomicAdd(&h1[b], 1);
        }
        for (int i = g; i < NTE; i += gs) {
            float p = sp[i];
            #pragma unroll
            for (int b = 0; b < NBINS; b++)
                if (p > bin_lo(b) && p <= bin_hi(b)) atomicAdd(&h2[b], 1);
        }
        __syncthreads();
        if (t < NBINS) { g_htr_part[blk][t] = h1[t]; g_hte_part[blk][t] = h2[t]; }
        if (t == 0) g_c_part[blk] = sc;
        return;
    }

    __shared__ int  hist[257 * SWARPS];
    __shared__ int  s_tot[257];
    __shared__ int  s_cs[258];
    __shared__ unsigned char s_flag[NMC];

    int task = blkid;
    const float2* src; int N; float4* dst;
    bool isq = false, isb = false;
    int bin = 0;
    if      (task == 0) { src = train; N = NTR;    dst = g_spts; }
    else if (task == 1) { src = test;  N = NTE;    dst = g_spts + NTR; }
    else if (task == 2) { src = batch; N = NBATCH; dst = g_spts + NTR + NTE; isb = true; }
    else { bin = task - 3; src = mc + bin * NMC; N = NMC; dst = g_qs + bin * NMC; isq = true; }

    unsigned lmask = (1u << lane) - 1u;

    for (int i = t; i < 257 * SWARPS; i += STHREADS) hist[i] = 0;
    __syncthreads();

    int iters = (N + STHREADS - 1) / STHREADS;
    float blo = bin_lo(bin), bhi = bin_hi(bin);

    for (int k = 0; k < iters; k++) {
        int i = k * STHREADS + t;
        int c = 256;
        if (i < N) {
            float2 p = src[i];
            if (isq) {
                float l[NCLS];
                float m = -1.0e30f;
                #pragma unroll
                for (int cc = 0; cc < NCLS; cc++) {
                    l[cc] = fmaf(p.x, __ldg(W + cc), fmaf(p.y, __ldg(W + NCLS + cc), __ldg(bvec + cc)));
                    m = fmaxf(m, l[cc]);
                }
                float ssum = 0.0f;
                #pragma unroll
                for (int cc = 0; cc < NCLS; cc++) ssum += __expf(l[cc] - m);
                float hat = 1.0f / ssum;
                int f = (hat >= blo && hat <= bhi) ? 1 : 0;
                s_flag[i] = (unsigned char)f;
                c = f ? cell_of_snake(p.x, p.y) : 256;
            }
            else if (isb) c = (y[i] != pred[i]) ? 256 : cell_of(p.x, p.y);
            else          c = cell_of(p.x, p.y);
        }
        unsigned m = __match_any_sync(0xffffffffu, c);
        int leader = __ffs(m) - 1;
        if (lane == leader) hist[c * SWARPS + w] += __popc(m);
    }
    __syncthreads();

    for (int c = w; c < 257; c += SWARPS) {
        int v = hist[c * SWARPS + lane];
        int incl = v;
        #pragma unroll
        for (int o = 1; o < 32; o <<= 1) {
            int n = __shfl_up_sync(0xffffffffu, incl, o);
            if (lane >= o) incl += n;
        }
        hist[c * SWARPS + lane] = incl - v;
        if (lane == 31) s_tot[c] = incl;
    }
    __syncthreads();
    if (t == 0) {
        int run = 0;
        for (int c = 0; c < 256; c++) { s_cs[c] = run; run += s_tot[c]; }
        s_cs[256] = run;
        if (isq) g_qn[bin] = run;
    }
    __syncthreads();
    if (!isq) {
        if (t < 256) g_cs_p[task][t] = s_cs[t];
        if (t == 0)  g_cs_p[task][256] = s_cs[256];
    }

    for (int k = 0; k < iters; k++) {
        int i = k * STHREADS + t;
        int c = 256;
        float2 p = make_float2(0.0f, 0.0f);
        if (i < N) {
            p = src[i];
            if (isq)      c = s_flag[i] ? cell_of_snake(p.x, p.y) : 256;
            else if (isb) c = (y[i] != pred[i]) ? 256 : cell_of(p.x, p.y);
            else          c = cell_of(p.x, p.y);
        }
        unsigned m = __match_any_sync(0xffffffffu, c);
        int leader = __ffs(m) - 1;
        int r = 0;
        if (lane == leader) {
            r = hist[c * SWARPS + w];
            hist[c * SWARPS + w] = r + __popc(m);
        }
        r = __shfl_sync(0xffffffffu, r, leader);
        if (c < 256) {
            int off = s_cs[c] + r + __popc(m & lmask);
            float s2 = p.x * p.x + p.y * p.y;
            dst[off] = isq ? make_float4(p.x, p.y, -CEXP * s2, 0.0f)
                           : make_float4(2.0f * CEXP * p.x, 2.0f * CEXP * p.y, -CEXP * s2, 0.0f);
        }
    }
}

// ---------------------------------------------------------------------------
// Plan: warp-per-qw in 1024-thread blocks; first warp folds prep partials.
// ---------------------------------------------------------------------------
__global__ __launch_bounds__(1024) void ec_plan() {
    int lane = threadIdx.x & 31;
    int qw = blockIdx.x * 32 + (threadIdx.x >> 5);
    if (qw >= NQWMAX) return;

    int qnb = (lane < NBINS) ? g_qn[lane] : 0;
    int nw  = (qnb + 31) / 32;
    int incl = nw;
    #pragma unroll
    for (int o = 1; o < 32; o <<= 1) {
        int n = __shfl_up_sync(0xffffffffu, incl, o);
        if (lane >= o) incl += n;
    }
    int ex  = incl - nw;
    int tot = __shfl_sync(0xffffffffu, incl, NBINS - 1);

    if (qw == 0) {
        if (lane == 0) { g_ntask = tot * NSLOT; g_task_ctr = 0; g_done = 0; }
        if (lane < NBINS) {
            g_wq_first[lane] = ex;
            int s1 = 0, s2 = 0;
            for (int p = 0; p < NPREP; p++) { s1 += g_htr_part[p][lane]; s2 += g_hte_part[p][lane]; }
            g_htr[lane] = s1; g_hte[lane] = s2;
        }
        if (lane == 31) {
            int s = 0;
            for (int p = 0; p < NPREP; p++) s += g_c_part[p];
            g_c = s;
        }
    }

    if (qw >= tot) return;

    int bin = 0;
    #pragma unroll
    for (int b = 0; b < NBINS; b++) {
        int fb = __shfl_sync(0xffffffffu, ex, b);
        if (qw >= fb) bin = b;
    }
    int first = __shfl_sync(0xffffffffu, ex, bin);
    if (lane == 0) g_wq_bin[qw] = bin;

    int lqw = qw - first;
    int qn  = __shfl_sync(0xffffffffu, qnb, bin);
    int qi  = lqw * 32 + lane;
    bool valid = qi < qn;
    float4 q = valid ? g_qs[bin * NMC + qi] : make_float4(0.0f, 0.0f, 0.0f, 0.0f);

    float xmn = valid ? q.x : 1.0e30f, xmx = valid ? q.x : -1.0e30f;
    float ymn = valid ? q.y : 1.0e30f, ymx = valid ? q.y : -1.0e30f;
    #pragma unroll
    for (int o = 16; o; o >>= 1) {
        xmn = fminf(xmn, __shfl_xor_sync(0xffffffffu, xmn, o));
        xmx = fmaxf(xmx, __shfl_xor_sync(0xffffffffu, xmx, o));
        ymn = fminf(ymn, __shfl_xor_sync(0xffffffffu, ymn, o));
        ymx = fmaxf(ymx, __shfl_xor_sync(0xffffffffu, ymx, o));
    }

    int cy0 = min(max((int)floorf((ymn - RC - DOMLO) * INVCELL), 0), GRIDW - 1);
    int cy1 = min(max((int)floorf((ymx + RC - DOMLO) * INVCELL), 0), GRIDW - 1);

    int myCy = cy0 + lane;
    int Ltr = 0, Lte = 0, Lb = 0, jtr0 = 0, jte0 = 0, jb0 = 0;
    if (myCy <= cy1) {
        float cyl = DOMLO + myCy * CELLSZ, cyh = cyl + CELLSZ;
        float dyv = fmaxf(0.0f, fmaxf(cyl - ymx, ymn - cyh));
        float d2 = RC * RC - dyv * dyv;
        if (d2 > 0.0f) {
            float dxv = sqrtf(d2);
            int cx0 = min(max((int)floorf((xmn - dxv - DOMLO) * INVCELL), 0), GRIDW - 1);
            int cx1 = min(max((int)floorf((xmx + dxv - DOMLO) * INVCELL), 0), GRIDW - 1);
            int ca = myCy * GRIDW + cx0, cb = myCy * GRIDW + cx1 + 1;
            jtr0 = g_cs_p[0][ca]; Ltr = g_cs_p[0][cb] - jtr0;
            jte0 = g_cs_p[1][ca]; Lte = g_cs_p[1][cb] - jte0;
            jb0  = g_cs_p[2][ca]; Lb  = g_cs_p[2][cb] - jb0;
        }
    }
    int rowTot = Ltr + Lte + Lb;
    int flag = (rowTot > 0) ? 1 : 0;

    int sT = rowTot, sF = flag;
    #pragma unroll
    for (int o = 1; o < 32; o <<= 1) {
        int nT = __shfl_up_sync(0xffffffffu, sT, o);
        int nF = __shfl_up_sync(0xffffffffu, sF, o);
        if (lane >= o) { sT += nT; sF += nF; }
    }
    int cum = sT - rowTot;
    int idx = sF - flag;
    int span = __shfl_sync(0xffffffffu, sT, 31);
    int nr   = __shfl_sync(0xffffffffu, sF, 31);

    if (flag) {
        g_qw_rowA[qw * MAXROWS + idx] = make_int4(cum, jtr0, jte0, jb0);
        g_qw_rowB[qw * MAXROWS + idx] = make_int4(Ltr, Lte, Lb, 0);
    }
    if (lane == 0) { g_qw_nrows[qw] = nr; g_qw_span[qw] = span; }
}

// ---------------------------------------------------------------------------
// Phase A: coalesced point loads + shfl broadcast; padded full-32 remainder
// ---------------------------------------------------------------------------
__device__ __forceinline__ float kde_span(const float4* __restrict__ pts,
                                          int j0, int j1, int lane,
                                          float qx, float qy, float qc, float acc)
{
    float acc2 = 0.0f;
    int j = j0;
    for (; j + 32 <= j1; j += 32) {
        float4 p = __ldg(pts + j + lane);
        #pragma unroll
        for (int k = 0; k < 32; k += 2) {
            float px0 = __shfl_sync(0xffffffffu, p.x, k);
            float py0 = __shfl_sync(0xffffffffu, p.y, k);
            float pz0 = __shfl_sync(0xffffffffu, p.z, k);
            float px1 = __shfl_sync(0xffffffffu, p.x, k + 1);
            float py1 = __shfl_sync(0xffffffffu, p.y, k + 1);
            float pz1 = __shfl_sync(0xffffffffu, p.z, k + 1);
            float t0 = fmaf(px0, qx, fmaf(py0, qy, pz0)) + qc;
            float t1 = fmaf(px1, qx, fmaf(py1, qy, pz1)) + qc;
            acc  += ex2f(t0);
            acc2 += ex2f(t1);
        }
    }
    int rem = j1 - j;
    if (rem > 0) {
        float4 p = (lane < rem) ? __ldg(pts + j + lane)
                                : make_float4(0.0f, 0.0f, -1.0e30f, 0.0f);
        #pragma unroll
        for (int k = 0; k < 32; k += 2) {
            float px0 = __shfl_sync(0xffffffffu, p.x, k);
            float py0 = __shfl_sync(0xffffffffu, p.y, k);
            float pz0 = __shfl_sync(0xffffffffu, p.z, k);
            float px1 = __shfl_sync(0xffffffffu, p.x, k + 1);
            float py1 = __shfl_sync(0xffffffffu, p.y, k + 1);
            float pz1 = __shfl_sync(0xffffffffu, p.z, k + 1);
            float t0 = fmaf(px0, qx, fmaf(py0, qy, pz0)) + qc;
            float t1 = fmaf(px1, qx, fmaf(py1, qy, pz1)) + qc;
            acc  += ex2f(t0);
            acc2 += ex2f(t1);
        }
    }
    return acc + acc2;
}

__global__ __launch_bounds__(512) void ec_phaseA()
{
    const int lane = threadIdx.x & 31;
    const int ntask = g_ntask;

    int   cached_qw = -1;
    float qx = 0.0f, qy = 0.0f, qc = -1.0e30f;

    while (true) {
        int tk = 0;
        if (lane == 0) tk = atomicAdd(&g_task_ctr, 1);
        tk = __shfl_sync(0xffffffffu, tk, 0);
        if (tk >= ntask) return;

        int qw = tk >> 6, slot = tk & (NSLOT - 1);
        int span = g_qw_span[qw];
        int lo = slot * CHPTS;
        if (lo >= span) continue;
        int hi = min(lo + CHPTS, span);

        if (qw != cached_qw) {
            cached_qw = qw;
            int bin = g_wq_bin[qw];
            int lqw = qw - g_wq_first[bin];
            int qn  = g_qn[bin];
            int qi  = lqw * 32 + lane;
            bool valid = qi < qn;
            float4 q = valid ? g_qs[bin * NMC + qi] : make_float4(0.0f, 0.0f, -1.0e30f, 0.0f);
            qx = q.x; qy = q.y; qc = q.z;
        }

        int nrows = g_qw_nrows[qw];
        float st = 0.0f, se = 0.0f, sb = 0.0f;

        for (int r = 0; r < nrows; r++) {
            int4 A = g_qw_rowA[qw * MAXROWS + r];
            if (A.x >= hi) break;
            int4 B = g_qw_rowB[qw * MAXROWS + r];
            int rowEnd = A.x + B.x + B.y + B.z;
            if (rowEnd <= lo) continue;

            int seg0 = A.x;
            {
                int a = max(lo - seg0, 0), b = min(hi - seg0, B.x);
                if (b > a) st = kde_span(g_spts, A.y + a, A.y + b, lane, qx, qy, qc, st);
                seg0 += B.x;
            }
            {
                int a = max(lo - seg0, 0), b = min(hi - seg0, B.y);
                if (b > a) se = kde_span(g_spts + NTR, A.z + a, A.z + b, lane, qx, qy, qc, se);
                seg0 += B.y;
            }
            {
                int a = max(lo - seg0, 0), b = min(hi - seg0, B.z);
                if (b > a) sb = kde_span(g_spts + NTR + NTE, A.w + a, A.w + b, lane, qx, qy, qc, sb);
            }
        }

        g_A[qw * 32 + lane][slot] = make_float4(st, se, sb, 0.0f);
    }
}

// ---------------------------------------------------------------------------
// Phase B v3: one 1024-thread block per qw; one WARP per query (32 warps =
// 32 queries of the qw). 2 coalesced loads + single shfl reduce per warp.
// Last block folds per-bin qw ranges into the final scalar.
// ---------------------------------------------------------------------------
__global__ __launch_bounds__(1024) void ec_phaseB(float* __restrict__ out)
{
    __shared__ double wsum[32];
    __shared__ double sbin[16];
    __shared__ bool amLast;
    int qw = blockIdx.x;
    int tid = threadIdx.x, w = tid >> 5, lane = tid & 31;
    int tot = g_ntask / NSLOT;

    double acc = 0.0;
    if (qw < tot) {
        int bin   = g_wq_bin[qw];
        int qn    = g_qn[bin];
        int first = g_wq_first[bin];
        int span  = g_qw_span[qw];
        int nslots = min((span + CHPTS - 1) / CHPTS, NSLOT);

        float cnt     = (float)g_c;
        float tr_rate = (float)g_htr[bin] * (1.0f / (float)NTR);
        float te_rate = (float)g_hte[bin] * (1.0f / (float)NTE);
        float p_y     = cnt * (1.0f / (float)NBATCH);
        float inv_cnt = 1.0f / (fmaxf(cnt, 1.0f) * KDE_NORM_F);

        int gqi = qw * 32 + w;
        const float4 Z = make_float4(0.0f, 0.0f, 0.0f, 0.0f);
        float4 a0 = (lane < nslots)      ? g_A[gqi][lane]      : Z;
        float4 a1 = (lane + 32 < nslots) ? g_A[gqi][lane + 32] : Z;

        float st = a0.x + a1.x;
        float se = a0.y + a1.y;
        float sb = a0.z + a1.z;
        #pragma unroll
        for (int o = 16; o; o >>= 1) {
            st += __shfl_xor_sync(0xffffffffu, st, o);
            se += __shfl_xor_sync(0xffffffffu, se, o);
            sb += __shfl_xor_sync(0xffffffffu, sb, o);
        }

        int k = (qw - first) * 32 + w;
        if (lane == 0 && k < qn) {
            float kde_tr = st * (1.0f / ((float)NTR * KDE_NORM_F));
            float kde_te = se * (1.0f / ((float)NTE * KDE_NORM_F));
            float kdw    = sb * inv_cnt;

            float d_t = (te_rate > 0.0f) ? (kde_te / te_rate) : 0.0f;
            float d_s = (tr_rate > 0.0f) ? (kde_tr / tr_rate) : 0.0f;

            float p_hs = kdw * p_y / (kde_tr + 1e-8f);
            p_hs = fminf(fmaxf(p_hs, 0.0f), 1.0f);
            acc = (double)(p_hs * (d_t - d_s));
        }
    }

    if (lane == 0) wsum[w] = acc;
    __syncthreads();
    if (w == 0) {
        double s = wsum[lane];
        #pragma unroll
        for (int o = 16; o; o >>= 1) s += __shfl_xor_sync(0xffffffffu, s, o);
        if (lane == 0) {
            g_partial[qw] = s;
            __threadfence();
            int v = atomicAdd(&g_done, 1);
            amLast = (v == gridDim.x - 1);
        }
    }
    __syncthreads();

    if (amLast) {
        for (int b = w; b < NBINS; b += 32) {
            int first = g_wq_first[b];
            int nw    = (g_qn[b] + 31) / 32;
            double s = 0.0;
            for (int c = lane; c < nw; c += 32) s += g_partial[first + c];
            #pragma unroll
            for (int o = 16; o; o >>= 1) s += __shfl_xor_sync(0xffffffffu, s, o);
            if (lane == 0) {
                double integral = s * (100.0 / (double)NMC);
                float te = (float)g_hte[b] * (1.0f / (float)NTE);
                sbin[b] = (te > 0.0f) ? (double)te * fabs(integral) : 0.0;
            }
        }
        __syncthreads();
        if (tid == 0) {
            double ec = 0.0;
            for (int b = 0; b < NBINS; b++) ec += sbin[b];
            out[0] = (float)ec;
        }
    }
}

// ---------------------------------------------------------------------------
extern "C" void kernel_launch(void* const* d_in, const int* in_sizes, int n_in,
                              void* d_out, int out_size) {
    const float *batch_x = nullptr, *train_probs = nullptr, *test_probs = nullptr;
    const float *train_x = nullptr, *test_x = nullptr, *W = nullptr, *bvec = nullptr, *mc = nullptr;
    const int   *y = nullptr, *pred = nullptr;

    for (int i = 0; i < n_in; i++) {
        int s = in_sizes[i];
        void* p = d_in[i];
        switch (s) {
            case 2048:   batch_x = (const float*)p; break;
            case 1024:   if (!y) y = (const int*)p; else pred = (const int*)p; break;
            case 20000:  if (!train_probs) train_probs = (const float*)p;
                         else test_x = (const float*)p; break;
            case 10000:  test_probs = (const float*)p; break;
            case 40000:  train_x = (const float*)p; break;
            case 20:     W = (const float*)p; break;
            case 10:     bvec = (const float*)p; break;
            case 300000: mc = (const float*)p; break;
            default: break;
        }
    }

    ec_sort<<<48, STHREADS>>>((const float2*)train_x, (const float2*)test_x,
                              (const float2*)batch_x, y, pred, (const float2*)mc,
                              W, bvec, train_probs, test_probs);
    ec_plan<<<(NQWMAX + 31) / 32, 1024>>>();
    ec_phaseA<<<NBLKA, 512>>>();
    ec_phaseB<<<NQWMAX, 1024>>>((float*)d_out);
}

// round 16
// speedup vs baseline: 1.0286x; 1.0286x over previous
#include <cuda_runtime.h>
#include <math.h>

#define NBINS   15
#define NTR     20000
#define NTE     10000
#define NBATCH  1024
#define NMC     10000
#define NCLS    10
#define NPTS_TOT (NTR + NTE + NBATCH)

#define GRIDW   16
#define CELLSZ  0.75f
#define INVCELL (1.0f / 0.75f)
#define DOMLO   (-6.0f)
#define RC      1.4f

#define CEXP       8.014972449383130f
#define KDE_NORM_F 0.56548667764616278f

#define NQWMAX  704
#define NSLOT   64           // CHPTS*NSLOT >= NPTS_TOT
#define CHPTS   512
#define NBLKA   296
#define MAXROWS 16

#define NPREP   30
#define STHREADS 1024
#define SWARPS   32
#define HSTRIDE  33          // padded stride: kills 32-way bank conflicts

#define NBLKB   (NQWMAX * 32 / 256)   // 88 blocks, 1 thread per query slot

__device__ int    g_htr_part[NPREP][NBINS];
__device__ int    g_hte_part[NPREP][NBINS];
__device__ int    g_c_part[NPREP];
__device__ int    g_htr[NBINS], g_hte[NBINS], g_c;
__device__ int    g_qn[NBINS];
__device__ int    g_cs_p[3][257];
__device__ int    g_wq_bin[NQWMAX];
__device__ int    g_wq_first[NBINS];
__device__ int    g_ntask, g_task_ctr, g_done;
__device__ int    g_qw_span[NQWMAX];
__device__ int    g_qw_nrows[NQWMAX];
__device__ int4   g_qw_rowA[NQWMAX * MAXROWS];   // {cum, jtr0, jte0, jb0}
__device__ int4   g_qw_rowB[NQWMAX * MAXROWS];   // {Ltr, Lte, Lb, 0}
__device__ float4 g_spts[NPTS_TOT];
__device__ float4 g_qs[NBINS * NMC];
__device__ float4 g_A[NSLOT][NQWMAX * 32];       // slot-major; unwritten slots stay 0
__device__ double g_partial[NQWMAX];

__device__ __forceinline__ float ex2f(float x) {
    float r;
    asm("ex2.approx.ftz.f32 %0, %1;" : "=f"(r) : "f"(x));
    return r;
}
__device__ __forceinline__ float bin_lo(int b) { return (float)b * (1.0f / 15.0f); }
__device__ __forceinline__ float bin_hi(int b) { return (b == NBINS - 1) ? 1.0f : (float)(b + 1) * (1.0f / 15.0f); }

__device__ __forceinline__ int cell_of(float x, float y) {
    int cx = min(max((int)floorf((x - DOMLO) * INVCELL), 0), GRIDW - 1);
    int cy = min(max((int)floorf((y - DOMLO) * INVCELL), 0), GRIDW - 1);
    return cy * GRIDW + cx;
}
__device__ __forceinline__ int cell_of_snake(float x, float y) {
    int cx = min(max((int)floorf((x - DOMLO) * INVCELL), 0), GRIDW - 1);
    int cy = min(max((int)floorf((y - DOMLO) * INVCELL), 0), GRIDW - 1);
    if (cy & 1) cx = GRIDW - 1 - cx;
    return cy * GRIDW + cx;
}

// ---------------------------------------------------------------------------
// Fused sort + prep. Blocks 0..17: counting sorts. Blocks 18..47: prep.
// Histogram stride padded to 33 -> conflict-free leader updates.
// ---------------------------------------------------------------------------
__global__ __launch_bounds__(STHREADS) void ec_sort(
    const float2* __restrict__ train, const float2* __restrict__ test,
    const float2* __restrict__ batch, const int* __restrict__ y,
    const int* __restrict__ pred, const float2* __restrict__ mc,
    const float* __restrict__ W, const float* __restrict__ bvec,
    const float* __restrict__ tp, const float* __restrict__ sp)
{
    int blkid = blockIdx.x;
    int t = threadIdx.x, w = t >> 5, lane = t & 31;

    if (blkid >= 18) {
        __shared__ int h1[NBINS], h2[NBINS], sc;
        int blk = blkid - 18;
        if (t < NBINS) { h1[t] = 0; h2[t] = 0; }
        if (t == 0) sc = 0;
        __syncthreads();

        int gs = NPREP * STHREADS;
        int g  = blk * STHREADS + t;

        int c = 0;
        for (int i = g; i < NBATCH; i += gs) c += (y[i] == pred[i]) ? 1 : 0;
        #pragma unroll
        for (int o = 16; o; o >>= 1) c += __shfl_xor_sync(0xffffffffu, c, o);
        if ((t & 31) == 0 && c) atomicAdd(&sc, c);

        for (int i = g; i < NTR; i += gs) {
            float p = tp[i];
            #pragma unroll
            for (int b = 0; b < NBINS; b++)
                if (p > bin_lo(b) && p <= bin_hi(b)) atomicAdd(&h1[b], 1);
        }
        for (int i = g; i < NTE; i += gs) {
            float p = sp[i];
            #pragma unroll
            for (int b = 0; b < NBINS; b++)
                if (p > bin_lo(b) && p <= bin_hi(b)) atomicAdd(&h2[b], 1);
        }
        __syncthreads();
        if (t < NBINS) { g_htr_part[blk][t] = h1[t]; g_hte_part[blk][t] = h2[t]; }
        if (t == 0) g_c_part[blk] = sc;
        return;
    }

    __shared__ int  hist[257 * HSTRIDE];
    __shared__ int  s_tot[257];
    __shared__ int  s_cs[258];
    __shared__ unsigned char s_flag[NMC];

    int task = blkid;
    const float2* src; int N; float4* dst;
    bool isq = false, isb = false;
    int bin = 0;
    if      (task == 0) { src = train; N = NTR;    dst = g_spts; }
    else if (task == 1) { src = test;  N = NTE;    dst = g_spts + NTR; }
    else if (task == 2) { src = batch; N = NBATCH; dst = g_spts + NTR + NTE; isb = true; }
    else { bin = task - 3; src = mc + bin * NMC; N = NMC; dst = g_qs + bin * NMC; isq = true; }

    unsigned lmask = (1u << lane) - 1u;

    for (int i = t; i < 257 * HSTRIDE; i += STHREADS) hist[i] = 0;
    __syncthreads();

    int iters = (N + STHREADS - 1) / STHREADS;
    float blo = bin_lo(bin), bhi = bin_hi(bin);

    for (int k = 0; k < iters; k++) {
        int i = k * STHREADS + t;
        int c = 256;
        if (i < N) {
            float2 p = src[i];
            if (isq) {
                float l[NCLS];
                float m = -1.0e30f;
                #pragma unroll
                for (int cc = 0; cc < NCLS; cc++) {
                    l[cc] = fmaf(p.x, __ldg(W + cc), fmaf(p.y, __ldg(W + NCLS + cc), __ldg(bvec + cc)));
                    m = fmaxf(m, l[cc]);
                }
                float ssum = 0.0f;
                #pragma unroll
                for (int cc = 0; cc < NCLS; cc++) ssum += __expf(l[cc] - m);
                float hat = 1.0f / ssum;
                int f = (hat >= blo && hat <= bhi) ? 1 : 0;
                s_flag[i] = (unsigned char)f;
                c = f ? cell_of_snake(p.x, p.y) : 256;
            }
            else if (isb) c = (y[i] != pred[i]) ? 256 : cell_of(p.x, p.y);
            else          c = cell_of(p.x, p.y);
        }
        unsigned m = __match_any_sync(0xffffffffu, c);
        int leader = __ffs(m) - 1;
        if (lane == leader) hist[c * HSTRIDE + w] += __popc(m);
    }
    __syncthreads();

    for (int c = w; c < 257; c += SWARPS) {
        int v = hist[c * HSTRIDE + lane];
        int incl = v;
        #pragma unroll
        for (int o = 1; o < 32; o <<= 1) {
            int n = __shfl_up_sync(0xffffffffu, incl, o);
            if (lane >= o) incl += n;
        }
        hist[c * HSTRIDE + lane] = incl - v;
        if (lane == 31) s_tot[c] = incl;
    }
    __syncthreads();
    if (t == 0) {
        int run = 0;
        for (int c = 0; c < 256; c++) { s_cs[c] = run; run += s_tot[c]; }
        s_cs[256] = run;
        if (isq) g_qn[bin] = run;
    }
    __syncthreads();
    if (!isq) {
        if (t < 256) g_cs_p[task][t] = s_cs[t];
        if (t == 0)  g_cs_p[task][256] = s_cs[256];
    }

    for (int k = 0; k < iters; k++) {
        int i = k * STHREADS + t;
        int c = 256;
        float2 p = make_float2(0.0f, 0.0f);
        if (i < N) {
            p = src[i];
            if (isq)      c = s_flag[i] ? cell_of_snake(p.x, p.y) : 256;
            else if (isb) c = (y[i] != pred[i]) ? 256 : cell_of(p.x, p.y);
            else          c = cell_of(p.x, p.y);
        }
        unsigned m = __match_any_sync(0xffffffffu, c);
        int leader = __ffs(m) - 1;
        int r = 0;
        if (lane == leader) {
            r = hist[c * HSTRIDE + w];
            hist[c * HSTRIDE + w] = r + __popc(m);
        }
        r = __shfl_sync(0xffffffffu, r, leader);
        if (c < 256) {
            int off = s_cs[c] + r + __popc(m & lmask);
            float s2 = p.x * p.x + p.y * p.y;
            dst[off] = isq ? make_float4(p.x, p.y, -CEXP * s2, 0.0f)
                           : make_float4(2.0f * CEXP * p.x, 2.0f * CEXP * p.y, -CEXP * s2, 0.0f);
        }
    }
}

// ---------------------------------------------------------------------------
// Plan: warp-per-qw in 1024-thread blocks; first warp folds prep partials.
// ---------------------------------------------------------------------------
__global__ __launch_bounds__(1024) void ec_plan() {
    int lane = threadIdx.x & 31;
    int qw = blockIdx.x * 32 + (threadIdx.x >> 5);
    if (qw >= NQWMAX) return;

    int qnb = (lane < NBINS) ? g_qn[lane] : 0;
    int nw  = (qnb + 31) / 32;
    int incl = nw;
    #pragma unroll
    for (int o = 1; o < 32; o <<= 1) {
        int n = __shfl_up_sync(0xffffffffu, incl, o);
        if (lane >= o) incl += n;
    }
    int ex  = incl - nw;
    int tot = __shfl_sync(0xffffffffu, incl, NBINS - 1);

    if (qw == 0) {
        if (lane == 0) { g_ntask = tot * NSLOT; g_task_ctr = 0; g_done = 0; }
        if (lane < NBINS) {
            g_wq_first[lane] = ex;
            int s1 = 0, s2 = 0;
            for (int p = 0; p < NPREP; p++) { s1 += g_htr_part[p][lane]; s2 += g_hte_part[p][lane]; }
            g_htr[lane] = s1; g_hte[lane] = s2;
        }
        if (lane == 31) {
            int s = 0;
            for (int p = 0; p < NPREP; p++) s += g_c_part[p];
            g_c = s;
        }
    }

    if (qw >= tot) return;

    int bin = 0;
    #pragma unroll
    for (int b = 0; b < NBINS; b++) {
        int fb = __shfl_sync(0xffffffffu, ex, b);
        if (qw >= fb) bin = b;
    }
    int first = __shfl_sync(0xffffffffu, ex, bin);
    if (lane == 0) g_wq_bin[qw] = bin;

    int lqw = qw - first;
    int qn  = __shfl_sync(0xffffffffu, qnb, bin);
    int qi  = lqw * 32 + lane;
    bool valid = qi < qn;
    float4 q = valid ? g_qs[bin * NMC + qi] : make_float4(0.0f, 0.0f, 0.0f, 0.0f);

    float xmn = valid ? q.x : 1.0e30f, xmx = valid ? q.x : -1.0e30f;
    float ymn = valid ? q.y : 1.0e30f, ymx = valid ? q.y : -1.0e30f;
    #pragma unroll
    for (int o = 16; o; o >>= 1) {
        xmn = fminf(xmn, __shfl_xor_sync(0xffffffffu, xmn, o));
        xmx = fmaxf(xmx, __shfl_xor_sync(0xffffffffu, xmx, o));
        ymn = fminf(ymn, __shfl_xor_sync(0xffffffffu, ymn, o));
        ymx = fmaxf(ymx, __shfl_xor_sync(0xffffffffu, ymx, o));
    }

    int cy0 = min(max((int)floorf((ymn - RC - DOMLO) * INVCELL), 0), GRIDW - 1);
    int cy1 = min(max((int)floorf((ymx + RC - DOMLO) * INVCELL), 0), GRIDW - 1);

    int myCy = cy0 + lane;
    int Ltr = 0, Lte = 0, Lb = 0, jtr0 = 0, jte0 = 0, jb0 = 0;
    if (myCy <= cy1) {
        float cyl = DOMLO + myCy * CELLSZ, cyh = cyl + CELLSZ;
        float dyv = fmaxf(0.0f, fmaxf(cyl - ymx, ymn - cyh));
        float d2 = RC * RC - dyv * dyv;
        if (d2 > 0.0f) {
            float dxv = sqrtf(d2);
            int cx0 = min(max((int)floorf((xmn - dxv - DOMLO) * INVCELL), 0), GRIDW - 1);
            int cx1 = min(max((int)floorf((xmx + dxv - DOMLO) * INVCELL), 0), GRIDW - 1);
            int ca = myCy * GRIDW + cx0, cb = myCy * GRIDW + cx1 + 1;
            jtr0 = g_cs_p[0][ca]; Ltr = g_cs_p[0][cb] - jtr0;
            jte0 = g_cs_p[1][ca]; Lte = g_cs_p[1][cb] - jte0;
            jb0  = g_cs_p[2][ca]; Lb  = g_cs_p[2][cb] - jb0;
        }
    }
    int rowTot = Ltr + Lte + Lb;
    int flag = (rowTot > 0) ? 1 : 0;

    int sT = rowTot, sF = flag;
    #pragma unroll
    for (int o = 1; o < 32; o <<= 1) {
        int nT = __shfl_up_sync(0xffffffffu, sT, o);
        int nF = __shfl_up_sync(0xffffffffu, sF, o);
        if (lane >= o) { sT += nT; sF += nF; }
    }
    int cum = sT - rowTot;
    int idx = sF - flag;
    int span = __shfl_sync(0xffffffffu, sT, 31);
    int nr   = __shfl_sync(0xffffffffu, sF, 31);

    if (flag) {
        g_qw_rowA[qw * MAXROWS + idx] = make_int4(cum, jtr0, jte0, jb0);
        g_qw_rowB[qw * MAXROWS + idx] = make_int4(Ltr, Lte, Lb, 0);
    }
    if (lane == 0) { g_qw_nrows[qw] = nr; g_qw_span[qw] = span; }
}

// ---------------------------------------------------------------------------
// Phase A: coalesced point loads + shfl broadcast; padded full-32 remainder
// ---------------------------------------------------------------------------
__device__ __forceinline__ float kde_span(const float4* __restrict__ pts,
                                          int j0, int j1, int lane,
                                          float qx, float qy, float qc, float acc)
{
    float acc2 = 0.0f;
    int j = j0;
    for (; j + 32 <= j1; j += 32) {
        float4 p = __ldg(pts + j + lane);
        #pragma unroll
        for (int k = 0; k < 32; k += 2) {
            float px0 = __shfl_sync(0xffffffffu, p.x, k);
            float py0 = __shfl_sync(0xffffffffu, p.y, k);
            float pz0 = __shfl_sync(0xffffffffu, p.z, k);
            float px1 = __shfl_sync(0xffffffffu, p.x, k + 1);
            float py1 = __shfl_sync(0xffffffffu, p.y, k + 1);
            float pz1 = __shfl_sync(0xffffffffu, p.z, k + 1);
            float t0 = fmaf(px0, qx, fmaf(py0, qy, pz0)) + qc;
            float t1 = fmaf(px1, qx, fmaf(py1, qy, pz1)) + qc;
            acc  += ex2f(t0);
            acc2 += ex2f(t1);
        }
    }
    int rem = j1 - j;
    if (rem > 0) {
        float4 p = (lane < rem) ? __ldg(pts + j + lane)
                                : make_float4(0.0f, 0.0f, -1.0e30f, 0.0f);
        #pragma unroll
        for (int k = 0; k < 32; k += 2) {
            float px0 = __shfl_sync(0xffffffffu, p.x, k);
            float py0 = __shfl_sync(0xffffffffu, p.y, k);
            float pz0 = __shfl_sync(0xffffffffu, p.z, k);
            float px1 = __shfl_sync(0xffffffffu, p.x, k + 1);
            float py1 = __shfl_sync(0xffffffffu, p.y, k + 1);
            float pz1 = __shfl_sync(0xffffffffu, p.z, k + 1);
            float t0 = fmaf(px0, qx, fmaf(py0, qy, pz0)) + qc;
            float t1 = fmaf(px1, qx, fmaf(py1, qy, pz1)) + qc;
            acc  += ex2f(t0);
            acc2 += ex2f(t1);
        }
    }
    return acc + acc2;
}

__global__ __launch_bounds__(512) void ec_phaseA()
{
    const int lane = threadIdx.x & 31;
    const int ntask = g_ntask;

    int   cached_qw = -1;
    float qx = 0.0f, qy = 0.0f, qc = -1.0e30f;

    while (true) {
        int tk = 0;
        if (lane == 0) tk = atomicAdd(&g_task_ctr, 1);
        tk = __shfl_sync(0xffffffffu, tk, 0);
        if (tk >= ntask) return;

        int qw = tk >> 6, slot = tk & (NSLOT - 1);
        int span = g_qw_span[qw];
        int lo = slot * CHPTS;
        if (lo >= span) continue;
        int hi = min(lo + CHPTS, span);

        if (qw != cached_qw) {
            cached_qw = qw;
            int bin = g_wq_bin[qw];
            int lqw = qw - g_wq_first[bin];
            int qn  = g_qn[bin];
            int qi  = lqw * 32 + lane;
            bool valid = qi < qn;
            float4 q = valid ? g_qs[bin * NMC + qi] : make_float4(0.0f, 0.0f, -1.0e30f, 0.0f);
            qx = q.x; qy = q.y; qc = q.z;
        }

        int nrows = g_qw_nrows[qw];
        float st = 0.0f, se = 0.0f, sb = 0.0f;

        for (int r = 0; r < nrows; r++) {
            int4 A = g_qw_rowA[qw * MAXROWS + r];
            if (A.x >= hi) break;
            int4 B = g_qw_rowB[qw * MAXROWS + r];
            int rowEnd = A.x + B.x + B.y + B.z;
            if (rowEnd <= lo) continue;

            int seg0 = A.x;
            {
                int a = max(lo - seg0, 0), b = min(hi - seg0, B.x);
                if (b > a) st = kde_span(g_spts, A.y + a, A.y + b, lane, qx, qy, qc, st);
                seg0 += B.x;
            }
            {
                int a = max(lo - seg0, 0), b = min(hi - seg0, B.y);
                if (b > a) se = kde_span(g_spts + NTR, A.z + a, A.z + b, lane, qx, qy, qc, se);
                seg0 += B.y;
            }
            {
                int a = max(lo - seg0, 0), b = min(hi - seg0, B.z);
                if (b > a) sb = kde_span(g_spts + NTR + NTE, A.w + a, A.w + b, lane, qx, qy, qc, sb);
            }
        }

        g_A[slot][qw * 32 + lane] = make_float4(st, se, sb, 0.0f);
    }
}

// ---------------------------------------------------------------------------
// Phase B v4: thread-per-query, fixed 64-slot unrolled fold over slot-major
// g_A (unwritten slots are zero); warp = one qw -> shfl double reduce;
// last block folds per-bin qw ranges into the final scalar.
// ---------------------------------------------------------------------------
__global__ __launch_bounds__(256) void ec_phaseB(float* __restrict__ out)
{
    __shared__ double sbin[16];
    __shared__ bool amLast;
    int tid = threadIdx.x, w = tid >> 5, lane = tid & 31;
    int gqi = blockIdx.x * 256 + tid;
    int qw  = gqi >> 5;

    float st = 0.0f, se = 0.0f, sb = 0.0f;
    #pragma unroll
    for (int s = 0; s < NSLOT; s++) {
        float4 a = g_A[s][gqi];
        st += a.x; se += a.y; sb += a.z;
    }

    int bin   = g_wq_bin[qw];
    int first = g_wq_first[bin];
    int qn    = g_qn[bin];
    int k     = (qw - first) * 32 + lane;

    float term = 0.0f;
    if (k < qn) {
        float cnt     = (float)g_c;
        float tr_rate = (float)g_htr[bin] * (1.0f / (float)NTR);
        float te_rate = (float)g_hte[bin] * (1.0f / (float)NTE);
        float p_y     = cnt * (1.0f / (float)NBATCH);

        float kde_tr = st * (1.0f / ((float)NTR * KDE_NORM_F));
        float kde_te = se * (1.0f / ((float)NTE * KDE_NORM_F));
        float kdw    = sb / (fmaxf(cnt, 1.0f) * KDE_NORM_F);

        float d_t = (te_rate > 0.0f) ? (kde_te / te_rate) : 0.0f;
        float d_s = (tr_rate > 0.0f) ? (kde_tr / tr_rate) : 0.0f;

        float p_hs = kdw * p_y / (kde_tr + 1e-8f);
        p_hs = fminf(fmaxf(p_hs, 0.0f), 1.0f);
        term = p_hs * (d_t - d_s);
    }

    double acc = (double)term;
    #pragma unroll
    for (int o = 16; o; o >>= 1) acc += __shfl_xor_sync(0xffffffffu, acc, o);
    if (lane == 0) g_partial[qw] = acc;

    __syncthreads();
    if (tid == 0) {
        __threadfence();
        int v = atomicAdd(&g_done, 1);
        amLast = (v == gridDim.x - 1);
    }
    __syncthreads();

    if (amLast) {
        for (int b = w; b < NBINS; b += 8) {
            int first2 = g_wq_first[b];
            int nw     = (g_qn[b] + 31) / 32;
            double s = 0.0;
            for (int c = lane; c < nw; c += 32) s += g_partial[first2 + c];
            #pragma unroll
            for (int o = 16; o; o >>= 1) s += __shfl_xor_sync(0xffffffffu, s, o);
            if (lane == 0) {
                double integral = s * (100.0 / (double)NMC);
                float te = (float)g_hte[b] * (1.0f / (float)NTE);
                sbin[b] = (te > 0.0f) ? (double)te * fabs(integral) : 0.0;
            }
        }
        __syncthreads();
        if (tid == 0) {
            double ec = 0.0;
            for (int b = 0; b < NBINS; b++) ec += sbin[b];
            out[0] = (float)ec;
        }
    }
}

// ---------------------------------------------------------------------------
extern "C" void kernel_launch(void* const* d_in, const int* in_sizes, int n_in,
                              void* d_out, int out_size) {
    const float *batch_x = nullptr, *train_probs = nullptr, *test_probs = nullptr;
    const float *train_x = nullptr, *test_x = nullptr, *W = nullptr, *bvec = nullptr, *mc = nullptr;
    const int   *y = nullptr, *pred = nullptr;

    for (int i = 0; i < n_in; i++) {
        int s = in_sizes[i];
        void* p = d_in[i];
        switch (s) {
            case 2048:   batch_x = (const float*)p; break;
            case 1024:   if (!y) y = (const int*)p; else pred = (const int*)p; break;
            case 20000:  if (!train_probs) train_probs = (const float*)p;
                         else test_x = (const float*)p; break;
            case 10000:  test_probs = (const float*)p; break;
            case 40000:  train_x = (const float*)p; break;
            case 20:     W = (const float*)p; break;
            case 10:     bvec = (const float*)p; break;
            case 300000: mc = (const float*)p; break;
            default: break;
        }
    }

    ec_sort<<<48, STHREADS>>>((const float2*)train_x, (const float2*)test_x,
                              (const float2*)batch_x, y, pred, (const float2*)mc,
                              W, bvec, train_probs, test_probs);
    ec_plan<<<(NQWMAX + 31) / 32, 1024>>>();
    ec_phaseA<<<NBLKA, 512>>>();
    ec_phaseB<<<NBLKB, 256>>>((float*)d_out);
}